// round 4
// baseline (speedup 1.0000x reference)
#include <cuda_runtime.h>
#include <cstdint>

#define NB       4
#define NN       2048
#define GEOM     32
#define KH       16          // GEOM/2 (f32x2-packed)
#define CLAMP_V  10.0f

typedef unsigned long long ull;

// Scratch for G = H @ W^T, [NB*NN, GEOM] floats = 1 MB (no allocs allowed)
__device__ __align__(16) float g_G[NB * NN * GEOM];

// ---------------- packed f32x2 helpers (sm_10x FFMA2 via PTX) ----------------
__device__ __forceinline__ ull ffma2(ull a, ull b, ull c) {
    ull d;
    asm("fma.rn.f32x2 %0, %1, %2, %3;" : "=l"(d) : "l"(a), "l"(b), "l"(c));
    return d;
}
__device__ __forceinline__ ull pack2(float x, float y) {
    ull r;
    asm("mov.b64 %0, {%1, %2};" : "=l"(r) : "f"(x), "f"(y));
    return r;
}
__device__ __forceinline__ float2 unpack2(ull v) {
    float2 f;
    asm("mov.b64 {%0, %1}, %2;" : "=f"(f.x), "=f"(f.y) : "l"(v));
    return f;
}
__device__ __forceinline__ float hadd2(ull v) {
    float2 f = unpack2(v);
    return f.x + f.y;
}

// ============================================================================
// Kernel 1: G[n][k] = sum_d H[n][d] * W[k][d]
// 128 blocks x 256 threads; tile 64 rows x 32 k; D chunked by 64 (32 d-pairs).
// Micro-tile 4 rows x 2 k: 6 LDS per 8 FFMA2 (was 9 per 8).
// ============================================================================
__global__ __launch_bounds__(256)
void geom_proj_kernel(const float* __restrict__ H, const float* __restrict__ W) {
    __shared__ ull Hs[64][33];   // [row][d-pair]
    __shared__ ull Ws[32][33];   // [k][d-pair]

    const int tid = threadIdx.x;
    const int kg  = tid & 15;    // k-group: k = kg*2 + {0,1}
    const int rg  = tid >> 4;    // row-group: rows rg*4 .. rg*4+3
    const int n0  = blockIdx.x * 64;

    const float4* __restrict__ H4 = (const float4*)H;
    const float4* __restrict__ W4 = (const float4*)W;

    float4 hreg[4];
    float4 wreg[2];

    // stage chunk 0 into registers
    #pragma unroll
    for (int p = 0; p < 4; p++) {
        int idx = tid + 256 * p;
        int row = idx >> 4, fc = idx & 15;
        hreg[p] = H4[(size_t)(n0 + row) * 256 + fc];
    }
    #pragma unroll
    for (int p = 0; p < 2; p++) {
        int idx = tid + 256 * p;
        int k = idx >> 4, fc = idx & 15;
        wreg[p] = W4[k * 256 + fc];
    }

    ull acc[4][2];
    #pragma unroll
    for (int r = 0; r < 4; r++) { acc[r][0] = 0ULL; acc[r][1] = 0ULL; }

    for (int c = 0; c < 16; c++) {
        __syncthreads();
        #pragma unroll
        for (int p = 0; p < 4; p++) {
            int idx = tid + 256 * p;
            int row = idx >> 4, fc = idx & 15;
            Hs[row][2 * fc]     = pack2(hreg[p].x, hreg[p].y);
            Hs[row][2 * fc + 1] = pack2(hreg[p].z, hreg[p].w);
        }
        #pragma unroll
        for (int p = 0; p < 2; p++) {
            int idx = tid + 256 * p;
            int k = idx >> 4, fc = idx & 15;
            Ws[k][2 * fc]     = pack2(wreg[p].x, wreg[p].y);
            Ws[k][2 * fc + 1] = pack2(wreg[p].z, wreg[p].w);
        }
        __syncthreads();

        if (c < 15) {   // prefetch next chunk behind compute
            #pragma unroll
            for (int p = 0; p < 4; p++) {
                int idx = tid + 256 * p;
                int row = idx >> 4, fc = idx & 15;
                hreg[p] = H4[(size_t)(n0 + row) * 256 + (c + 1) * 16 + fc];
            }
            #pragma unroll
            for (int p = 0; p < 2; p++) {
                int idx = tid + 256 * p;
                int k = idx >> 4, fc = idx & 15;
                wreg[p] = W4[k * 256 + (c + 1) * 16 + fc];
            }
        }

        #pragma unroll
        for (int dc = 0; dc < 32; dc++) {
            ull w0 = Ws[kg * 2][dc];
            ull w1 = Ws[kg * 2 + 1][dc];
            #pragma unroll
            for (int r = 0; r < 4; r++) {
                ull h = Hs[rg * 4 + r][dc];
                acc[r][0] = ffma2(h, w0, acc[r][0]);
                acc[r][1] = ffma2(h, w1, acc[r][1]);
            }
        }
    }

    // coalesced float2 stores: lanes kg 0..15 cover a contiguous 128B row span
    float2* __restrict__ G2o = (float2*)g_G;
    #pragma unroll
    for (int r = 0; r < 4; r++) {
        float2 v;
        v.x = hadd2(acc[r][0]);
        v.y = hadd2(acc[r][1]);
        G2o[(size_t)(n0 + rg * 4 + r) * KH + kg] = v;
    }
}

// ============================================================================
// Kernel 2: out[b,i,j] = clamp(alpha*Bprev - beta*max(0, Gsq_i+Gsq_j-2*G_i.G_j))
// Grid (32,16,4), 128 threads, 128(i) x 64(j) tile, 8x8 register micro-tile.
// LDS per FFMA2 = 0.125 (was 0.5) -> L1 stops binding; DRAM becomes limiter.
// ============================================================================
__global__ __launch_bounds__(128, 2)
void bias_update_kernel(const float* __restrict__ Bprev,
                        const float* __restrict__ alpha_p,
                        const float* __restrict__ beta_p,
                        float* __restrict__ Out) {
    __shared__ ull GiT[16][131];   // [kpair][i], pad 131: conflict-free stores+reads
    __shared__ ull GjT[16][67];    // [kpair][j], pad 67
    __shared__ float GsqI[128];
    __shared__ float GsqJ[64];

    const int tid = threadIdx.x;
    const int tx  = tid & 7;       // j = tx + 8*jj
    const int ty  = tid >> 3;      // i = ty + 16*ii   (0..15)
    const int b   = blockIdx.z;
    const int i0  = blockIdx.y * 128;
    const int j0  = blockIdx.x * 64;

    const ull* __restrict__ G2 = (const ull*)g_G;
    const size_t gbase = (size_t)b * NN * KH;     // u64 units
    const size_t obase = (size_t)b * NN * NN;

    // Stage G tiles (all LDGs issued up front for MLP)
    ull gi[16], gj[8];
    #pragma unroll
    for (int p = 0; p < 16; p++) {
        int idx = tid + 128 * p;
        int row = idx >> 4, kk = idx & 15;
        gi[p] = G2[gbase + (size_t)(i0 + row) * KH + kk];
    }
    #pragma unroll
    for (int p = 0; p < 8; p++) {
        int idx = tid + 128 * p;
        int row = idx >> 4, kk = idx & 15;
        gj[p] = G2[gbase + (size_t)(j0 + row) * KH + kk];
    }
    const float alpha = __ldg(alpha_p);
    const float beta  = __ldg(beta_p);

    #pragma unroll
    for (int p = 0; p < 16; p++) {
        int idx = tid + 128 * p;
        int row = idx >> 4, kk = idx & 15;
        GiT[kk][row] = gi[p];
    }
    #pragma unroll
    for (int p = 0; p < 8; p++) {
        int idx = tid + 128 * p;
        int row = idx >> 4, kk = idx & 15;
        GjT[kk][row] = gj[p];
    }
    __syncthreads();

    // Row squared-norms from the resident tiles
    {
        float s = 0.f;
        #pragma unroll
        for (int kk = 0; kk < 16; kk++) {
            float2 v = unpack2(GiT[kk][tid]);
            s += v.x * v.x + v.y * v.y;
        }
        GsqI[tid] = s;
    }
    if (tid < 64) {
        float s = 0.f;
        #pragma unroll
        for (int kk = 0; kk < 16; kk++) {
            float2 v = unpack2(GjT[kk][tid]);
            s += v.x * v.x + v.y * v.y;
        }
        GsqJ[tid] = s;
    }
    __syncthreads();

    // 8x8 Gram micro-tile (f32x2 packed over k)
    ull acc[8][8];
    #pragma unroll
    for (int ii = 0; ii < 8; ii++)
        #pragma unroll
        for (int jj = 0; jj < 8; jj++) acc[ii][jj] = 0ULL;

    #pragma unroll
    for (int kk = 0; kk < 16; kk++) {
        ull av[8], bv[8];
        #pragma unroll
        for (int ii = 0; ii < 8; ii++) av[ii] = GiT[kk][ty + 16 * ii];
        #pragma unroll
        for (int jj = 0; jj < 8; jj++) bv[jj] = GjT[kk][tx + 8 * jj];
        #pragma unroll
        for (int ii = 0; ii < 8; ii++)
            #pragma unroll
            for (int jj = 0; jj < 8; jj++)
                acc[ii][jj] = ffma2(av[ii], bv[jj], acc[ii][jj]);
    }

    // Epilogue: stream Bprev -> clamp -> Out (coalesced 32B sectors)
    #pragma unroll
    for (int ii = 0; ii < 8; ii++) {
        const int row = i0 + ty + 16 * ii;
        const float* __restrict__ bpr = Bprev + obase + (size_t)row * NN + j0;
        float* __restrict__ opr = Out + obase + (size_t)row * NN + j0;
        const float si = GsqI[ty + 16 * ii];

        float bp[8];
        #pragma unroll
        for (int jj = 0; jj < 8; jj++)
            bp[jj] = __ldg(bpr + tx + 8 * jj);

        #pragma unroll
        for (int jj = 0; jj < 8; jj++) {
            float2 v = unpack2(acc[ii][jj]);
            float dist = si + GsqJ[tx + 8 * jj] - 2.0f * (v.x + v.y);
            dist = fmaxf(dist, 0.0f);
            float o = alpha * bp[jj] - beta * dist;
            o = fminf(fmaxf(o, -CLAMP_V), CLAMP_V);
            opr[tx + 8 * jj] = o;
        }
    }
}

// ============================================================================
extern "C" void kernel_launch(void* const* d_in, const int* in_sizes, int n_in,
                              void* d_out, int out_size) {
    const float* H     = (const float*)d_in[0];   // [4,2048,1024]
    const float* Bprev = (const float*)d_in[1];   // [4,2048,2048]
    const float* W     = (const float*)d_in[2];   // [32,1024]
    const float* alpha = (const float*)d_in[3];   // scalar
    const float* beta  = (const float*)d_in[4];   // scalar
    float* Out = (float*)d_out;

    geom_proj_kernel<<<(NB * NN) / 64, 256>>>(H, W);
    bias_update_kernel<<<dim3(NN / 64, NN / 128, NB), 128>>>(Bprev, alpha, beta, Out);
}